// round 11
// baseline (speedup 1.0000x reference)
#include <cuda_runtime.h>
#include <cuda_bf16.h>

// CRF forward, scaled-probability domain. FOUR batches per warp as TWO
// independent f32x2-packed chains, interleaved so each chain's exposed
// stall cycles are filled by the other chain's instruction stream.
//
//   feats      : (512, 1024, 32) f32
//   mask       : (512, 1024)     f32  (0/1 semantics)
//   transition : (32, 32)        f32
//   out        : (1024,)         f32
//
// alpha_t[j] = feat[t,b,j] + logsumexp_i(alpha_{t-1}[i] + T[j,i])
// p = exp(alpha - M), E' = 2^-6 exp(T):  q = E' p ;  p' = q*(m*ef) + p*(1-m)
// Prescale 2^-6 absorbs mean growth -> renorm period 16. Correction exact:
// out += cnt*6ln2, cnt = sum(mask)  (off-chain FADD/step).
//
// Renorm: delayed-apply period 16; snapshot max off-chain, apply 1/s one
// period later (one packed MUL on-chain). 4 butterflies interleaved.
//
// Loads: 4 feat LDG/step (8-deep reg ring/chain; per-register rewrite
// distance 8 steps >> DRAM latency). Mask: 1 LDG per lane per 16 steps
// (all 32 lanes cover 16 steps x 2 pairs), broadcast LDS.64 per step.
//
// 256 warps = 128 blocks x 64 threads -> 2 warps/SM, SMSP-private chains,
// halved per-SM LSU contention vs 4-warp blocks.

#define SEQ   512
#define BATCH 1024
#define TAGS  32
#define START_TAG 30
#define END_TAG   31
#define WPB   2
#define TPB   64
#define NBLOCKS 128
#define PERIOD 16
#define RING  8

#define CPRE        0.015625f                 // 2^-6 exact
#define LOG_CPREINV 4.1588830833596718f       // 6*ln2

typedef unsigned long long u64;

__device__ __forceinline__ u64 pack2(float lo, float hi) {
    u64 r; asm("mov.b64 %0, {%1, %2};" : "=l"(r) : "f"(lo), "f"(hi)); return r;
}
__device__ __forceinline__ void unpack2(u64 v, float& lo, float& hi) {
    asm("mov.b64 {%0, %1}, %2;" : "=f"(lo), "=f"(hi) : "l"(v));
}
__device__ __forceinline__ u64 fma2(u64 a, u64 b, u64 c) {
    u64 r; asm("fma.rn.f32x2 %0, %1, %2, %3;" : "=l"(r) : "l"(a), "l"(b), "l"(c)); return r;
}
__device__ __forceinline__ u64 add2(u64 a, u64 b) {
    u64 r; asm("add.rn.f32x2 %0, %1, %2;" : "=l"(r) : "l"(a), "l"(b)); return r;
}
__device__ __forceinline__ u64 mul2(u64 a, u64 b) {
    u64 r; asm("mul.rn.f32x2 %0, %1, %2;" : "=l"(r) : "l"(a), "l"(b)); return r;
}

__global__ __launch_bounds__(TPB, 1)
void crf_fwd_kernel(const float* __restrict__ feats,
                    const float* __restrict__ mask,
                    const float* __restrict__ trans,
                    float* __restrict__ out)
{
    const int j  = threadIdx.x & 31;          // tag / lane
    const int w  = threadIdx.x >> 5;          // warp in block (0..1)
    const int g  = blockIdx.x * WPB + w;      // global warp id (0..255)
    const int b0 = 4 * g;                     // batches b0..b0+3

    // packed p broadcast: [warp][chain][tag]
    __shared__ __align__(16) u64    sp[WPB][2][TAGS];
    // mask chunk stage: [warp][buf][pair][step-in-chunk]
    __shared__ __align__(8)  float2 mbuf[WPB][2][2][PERIOD];

    // ---- E row j, prescaled, duplicated into both halves (shared) --------
    u64 e2[TAGS];
#pragma unroll
    for (int i = 0; i < TAGS; ++i) {
        const float e = __expf(trans[j * TAGS + i]) * CPRE;
        e2[i] = pack2(e, e);
    }
    const float eEnd = __expf(trans[END_TAG * TAGS + j]);

    // ---- init ------------------------------------------------------------
    const float pinit = (j == START_TAG) ? 1.0f : 0.0f;
    u64 pC = pack2(pinit, pinit);
    u64 pD = pack2(pinit, pinit);
    float M0 = 0.f, M1 = 0.f, M2 = 0.f, M3 = 0.f;
    float cnt0 = 0.f, cnt1 = 0.f, cnt2 = 0.f, cnt3 = 0.f;
    u64 invC = pack2(1.0f, 1.0f);
    u64 invD = pack2(1.0f, 1.0f);
    sp[w][0][j] = pC;
    sp[w][1][j] = pD;

    // ---- feat rings (8 deep, 4 LDG/step) ---------------------------------
    const int fbA = (b0 + 0) * TAGS + j;
    const int fbB = (b0 + 1) * TAGS + j;
    const int fbC = (b0 + 2) * TAGS + j;
    const int fbD = (b0 + 3) * TAGS + j;
    float rA[RING], rB[RING], rC[RING], rD[RING];
#pragma unroll
    for (int s = 0; s < RING; ++s) {
        rA[s] = feats[s * (BATCH * TAGS) + fbA];
        rB[s] = feats[s * (BATCH * TAGS) + fbB];
        rC[s] = feats[s * (BATCH * TAGS) + fbC];
        rD[s] = feats[s * (BATCH * TAGS) + fbD];
    }

    // ---- mask staging: all 32 lanes cover 16 steps x 2 pairs -------------
    const float2* __restrict__ MK2 = reinterpret_cast<const float2*>(mask);
    const int lpair = j >> 4;                 // 0: pair(b0,b0+1), 1: pair(b0+2,b0+3)
    const int lstep = j & 15;
    const int pidx  = 2 * g + lpair;          // global float2 pair index
    mbuf[w][0][lpair][lstep] = MK2[lstep * (BATCH / 2) + pidx];
    float2 mreg = MK2[(PERIOD + lstep) * (BATCH / 2) + pidx];
    __syncwarp();                             // sp + mbuf visible

    // ---- prepare step 0 (em/om one step ahead of use) --------------------
    float2 mnC = mbuf[w][0][0][0];
    float2 mnD = mbuf[w][0][1][0];
    u64 emC = pack2(mnC.x * __expf(rA[0]), mnC.y * __expf(rB[0]));
    u64 omC = pack2(1.0f - mnC.x, 1.0f - mnC.y);
    u64 emD = pack2(mnD.x * __expf(rC[0]), mnD.y * __expf(rD[0]));
    u64 omD = pack2(1.0f - mnD.x, 1.0f - mnD.y);

    // ---- main recurrence: 32 chunks x 16 unrolled steps ------------------
    for (int blk = 0; blk < SEQ / PERIOD; ++blk) {
        const int t0 = blk * PERIOD;

#pragma unroll
        for (int u = 0; u < PERIOD; ++u) {
            const u64 emCc = emC, omCc = omC;
            const u64 emDc = emD, omDc = omD;
            const float2 mcC = mnC, mcD = mnD;

            // ---- mask chunk rotation, once per chunk ---------------------
            if (u == 0) {
                mbuf[w][(blk + 1) & 1][lpair][lstep] = mreg;     // stage blk+1
                const int cn = ((blk + 2) & 31) * PERIOD;        // load blk+2
                mreg = MK2[(cn + lstep) * (BATCH / 2) + pidx];
            }

            // ---- prepare em/om for step t+1 ------------------------------
            {
                const int slot = (u + 1) & (RING - 1);
                const int nb = (u == PERIOD - 1) ? ((blk + 1) & 1) : (blk & 1);
                const int ns = (u + 1) & (PERIOD - 1);
                const float2 mC2 = mbuf[w][nb][0][ns];
                const float2 mD2 = mbuf[w][nb][1][ns];
                emC = pack2(mC2.x * __expf(rA[slot]), mC2.y * __expf(rB[slot]));
                omC = pack2(1.0f - mC2.x, 1.0f - mC2.y);
                emD = pack2(mD2.x * __expf(rC[slot]), mD2.y * __expf(rD[slot]));
                omD = pack2(1.0f - mD2.x, 1.0f - mD2.y);
                mnC = mC2;
                mnD = mD2;
            }

            // ---- refill ring slot (u&7) with step t+8 --------------------
            {
                const int tp = (t0 + u + RING) & (SEQ - 1);
                const int sl = u & (RING - 1);
                rA[sl] = feats[tp * (BATCH * TAGS) + fbA];
                rB[sl] = feats[tp * (BATCH * TAGS) + fbB];
                rC[sl] = feats[tp * (BATCH * TAGS) + fbC];
                rD[sl] = feats[tp * (BATCH * TAGS) + fbD];
            }

            asm volatile("" ::: "memory");     // keep prior STS before LDS

            // ---- two interleaved packed matvecs --------------------------
            const ulonglong2* __restrict__ srcC =
                reinterpret_cast<const ulonglong2*>(sp[w][0]);
            const ulonglong2* __restrict__ srcD =
                reinterpret_cast<const ulonglong2*>(sp[w][1]);
            u64 a0 = 0, a1 = 0, a2 = 0, a3 = 0;   // chain C accums
            u64 d0 = 0, d1 = 0, d2 = 0, d3 = 0;   // chain D accums
#pragma unroll
            for (int h = 0; h < 4; ++h) {
                const ulonglong2 vc0 = srcC[4 * h + 0];
                const ulonglong2 vd0 = srcD[4 * h + 0];
                const ulonglong2 vc1 = srcC[4 * h + 1];
                const ulonglong2 vd1 = srcD[4 * h + 1];
                const ulonglong2 vc2 = srcC[4 * h + 2];
                const ulonglong2 vd2 = srcD[4 * h + 2];
                const ulonglong2 vc3 = srcC[4 * h + 3];
                const ulonglong2 vd3 = srcD[4 * h + 3];
                a0 = fma2(e2[8 * h + 0], vc0.x, a0);
                d0 = fma2(e2[8 * h + 0], vd0.x, d0);
                a1 = fma2(e2[8 * h + 1], vc0.y, a1);
                d1 = fma2(e2[8 * h + 1], vd0.y, d1);
                a2 = fma2(e2[8 * h + 2], vc1.x, a2);
                d2 = fma2(e2[8 * h + 2], vd1.x, d2);
                a3 = fma2(e2[8 * h + 3], vc1.y, a3);
                d3 = fma2(e2[8 * h + 3], vd1.y, d3);
                a0 = fma2(e2[8 * h + 4], vc2.x, a0);
                d0 = fma2(e2[8 * h + 4], vd2.x, d0);
                a1 = fma2(e2[8 * h + 5], vc2.y, a1);
                d1 = fma2(e2[8 * h + 5], vd2.y, d1);
                a2 = fma2(e2[8 * h + 6], vc3.x, a2);
                d2 = fma2(e2[8 * h + 6], vd3.x, d2);
                a3 = fma2(e2[8 * h + 7], vc3.y, a3);
                d3 = fma2(e2[8 * h + 7], vd3.y, d3);
            }
            const u64 qC = add2(add2(a0, a1), add2(a2, a3));
            const u64 qD = add2(add2(d0, d1), add2(d2, d3));

            // ---- packed tails: p' = q*em + p*om --------------------------
            pC = fma2(qC, emCc, mul2(pC, omCc));
            pD = fma2(qD, emDc, mul2(pD, omDc));

            // ---- applied-step counters (off-chain) -----------------------
            cnt0 += mcC.x;  cnt1 += mcC.y;
            cnt2 += mcD.x;  cnt3 += mcD.y;

            // ---- delayed renorm, period 16 -------------------------------
            if (u == PERIOD - 1) {
                pC = mul2(pC, invC);           // apply PREVIOUS scales
                pD = mul2(pD, invD);
                float s0, s1, s2, s3;
                unpack2(pC, s0, s1);
                unpack2(pD, s2, s3);
#pragma unroll
                for (int off = 16; off > 0; off >>= 1) {
                    const float t0v = __shfl_xor_sync(0xffffffffu, s0, off);
                    const float t1v = __shfl_xor_sync(0xffffffffu, s1, off);
                    const float t2v = __shfl_xor_sync(0xffffffffu, s2, off);
                    const float t3v = __shfl_xor_sync(0xffffffffu, s3, off);
                    s0 = fmaxf(s0, t0v);
                    s1 = fmaxf(s1, t1v);
                    s2 = fmaxf(s2, t2v);
                    s3 = fmaxf(s3, t3v);
                }
                M0 += __logf(s0);
                M1 += __logf(s1);
                M2 += __logf(s2);
                M3 += __logf(s3);
                invC = pack2(__frcp_rn(s0), __frcp_rn(s1));
                invD = pack2(__frcp_rn(s2), __frcp_rn(s3));
            }

            sp[w][0][j] = pC;                  // publish for next step
            sp[w][1][j] = pD;
        }
    }

    // ---- epilogue --------------------------------------------------------
    pC = mul2(pC, invC);
    pD = mul2(pD, invD);
    float p0, p1, p2v, p3v;
    unpack2(pC, p0, p1);
    unpack2(pD, p2v, p3v);
    float x0 = p0 * eEnd, x1 = p1 * eEnd, x2 = p2v * eEnd, x3 = p3v * eEnd;
#pragma unroll
    for (int off = 16; off > 0; off >>= 1) {
        x0 += __shfl_xor_sync(0xffffffffu, x0, off);
        x1 += __shfl_xor_sync(0xffffffffu, x1, off);
        x2 += __shfl_xor_sync(0xffffffffu, x2, off);
        x3 += __shfl_xor_sync(0xffffffffu, x3, off);
    }
    if (j == 0) {
        out[b0 + 0] = M0 + __logf(x0) + cnt0 * LOG_CPREINV;
        out[b0 + 1] = M1 + __logf(x1) + cnt1 * LOG_CPREINV;
        out[b0 + 2] = M2 + __logf(x2) + cnt2 * LOG_CPREINV;
        out[b0 + 3] = M3 + __logf(x3) + cnt3 * LOG_CPREINV;
    }
}

extern "C" void kernel_launch(void* const* d_in, const int* in_sizes, int n_in,
                              void* d_out, int out_size)
{
    const float* feats = (const float*)d_in[0];
    const float* msk   = (const float*)d_in[1];
    const float* trans = (const float*)d_in[2];
    float*       o     = (float*)d_out;

    crf_fwd_kernel<<<NBLOCKS, TPB>>>(feats, msk, trans, o);
}

// round 15
// speedup vs baseline: 1.7902x; 1.7902x over previous
#include <cuda_runtime.h>
#include <cuda_bf16.h>

// CRF forward, scaled-probability domain, f32x2-packed (2 batches/warp),
// BLOCK-COOPERATIVE chunk staging: zero LDG in the per-step loop.
//
//   feats      : (512, 1024, 32) f32
//   mask       : (512, 1024)     f32  (0/1 semantics)
//   transition : (32, 32)        f32
//   out        : (1024,)         f32
//
// alpha_t[j] = feat[t,b,j] + logsumexp_i(alpha_{t-1}[i] + T[j,i])
// p = exp(alpha - M), E' = 2^-6 exp(T):  q = E' p ; p' = q*(m*ef) + p*(1-m)
// 2^-6 prescale -> renorm period 16; correction exact: out += cnt*6ln2.
//
// Staging: the block's 4 warps cooperatively load 8 timesteps x 8 batches
// of feats (8KB) + mask into double-buffered smem. LDGs for chunk c+2 are
// issued at the start of chunk c's processing and consumed by STS one full
// chunk (~2000 cyc) later -> the LDG scoreboard wait never lands on the
// recurrence. The per-step loop reads feats/mask via LDS only.
//
// Renorm: delayed-apply, period 16 (snapshot max off-chain, apply 1/s one
// period later). Validated rel_err ~1.4e-7.
//
// 512 warps = 128 blocks x 128 threads -> 1 warp/SMSP on 128 SMs.

#define SEQ   512
#define BATCH 1024
#define TAGS  32
#define START_TAG 30
#define END_TAG   31
#define WPB   4
#define TPB   128
#define NBLOCKS 128
#define CHUNK  8
#define NCHUNK (SEQ / CHUNK)      // 64

#define CPRE        0.015625f                 // 2^-6 exact
#define LOG_CPREINV 4.1588830833596718f       // 6*ln2

typedef unsigned long long u64;

__device__ __forceinline__ u64 pack2(float lo, float hi) {
    u64 r; asm("mov.b64 %0, {%1, %2};" : "=l"(r) : "f"(lo), "f"(hi)); return r;
}
__device__ __forceinline__ void unpack2(u64 v, float& lo, float& hi) {
    asm("mov.b64 {%0, %1}, %2;" : "=f"(lo), "=f"(hi) : "l"(v));
}
__device__ __forceinline__ u64 fma2(u64 a, u64 b, u64 c) {
    u64 r; asm("fma.rn.f32x2 %0, %1, %2, %3;" : "=l"(r) : "l"(a), "l"(b), "l"(c)); return r;
}
__device__ __forceinline__ u64 add2(u64 a, u64 b) {
    u64 r; asm("add.rn.f32x2 %0, %1, %2;" : "=l"(r) : "l"(a), "l"(b)); return r;
}
__device__ __forceinline__ u64 mul2(u64 a, u64 b) {
    u64 r; asm("mul.rn.f32x2 %0, %1, %2;" : "=l"(r) : "l"(a), "l"(b)); return r;
}

__global__ __launch_bounds__(TPB, 1)
void crf_fwd_kernel(const float* __restrict__ feats,
                    const float* __restrict__ mask,
                    const float* __restrict__ trans,
                    float* __restrict__ out)
{
    const int tid  = threadIdx.x;
    const int j    = tid & 31;                 // tag / lane
    const int w    = tid >> 5;                 // warp in block
    const int bblk = blockIdx.x * 8;           // block's first batch
    const int b0   = bblk + 2 * w;             // this warp's batch pair

    __shared__ __align__(16) u64   sp[WPB][TAGS];           // packed p
    __shared__ __align__(16) float fbuf[2][CHUNK][8 * TAGS]; // 16KB feats
    __shared__ __align__(8)  float mkbuf[2][CHUNK][8];       // mask

    // ---- E row j, prescaled, duplicated into both halves -----------------
    u64 e2[TAGS];
#pragma unroll
    for (int i = 0; i < TAGS; ++i) {
        const float e = __expf(trans[j * TAGS + i]) * CPRE;
        e2[i] = pack2(e, e);
    }
    const float eEnd = __expf(trans[END_TAG * TAGS + j]);

    // ---- init ------------------------------------------------------------
    const float pinit = (j == START_TAG) ? 1.0f : 0.0f;
    u64 p2 = pack2(pinit, pinit);
    float M0 = 0.f, M1 = 0.f;
    float cnt0 = 0.f, cnt1 = 0.f;
    u64 pinv2 = pack2(1.0f, 1.0f);
    sp[w][j] = p2;

    // ---- staging geometry -------------------------------------------------
    const int srow = tid >> 4;                 // 0..7 : timestep in chunk
    const int scol = tid & 15;                 // 0..15: float4 column
    const float4* __restrict__ F4 = reinterpret_cast<const float4*>(feats);
    const int rs4   = BATCH * TAGS / 4;        // 8192 float4 per timestep
    const int cb4   = blockIdx.x * 64;         // block column base (float4)
    const int mt    = (tid >> 3) & 7;          // mask: timestep in chunk
    const int mb    = tid & 7;                 // mask: batch in block

    // ---- prologue: chunk 0 -> buf0 directly; LDG chunk 1 -> regs ---------
    {
        float4* dst = reinterpret_cast<float4*>(fbuf[0][srow]);
#pragma unroll
        for (int k = 0; k < 4; ++k)
            dst[scol + 16 * k] = F4[srow * rs4 + cb4 + scol + 16 * k];
        mkbuf[0][mt][mb] = mask[mt * BATCH + bblk + mb];
    }
    float4 rv[4];
    float  rm;
#pragma unroll
    for (int k = 0; k < 4; ++k)
        rv[k] = F4[(CHUNK + srow) * rs4 + cb4 + scol + 16 * k];
    rm = mask[(CHUNK + mt) * BATCH + bblk + mb];
    __syncthreads();

    // ---- prepare step 0 (em/om one step ahead of use) --------------------
    float mxx = mkbuf[0][0][2 * w];
    float myy = mkbuf[0][0][2 * w + 1];
    u64 em2 = pack2(mxx * __expf(fbuf[0][0][2 * w * TAGS + j]),
                    myy * __expf(fbuf[0][0][(2 * w + 1) * TAGS + j]));
    u64 om2 = pack2(1.0f - mxx, 1.0f - myy);

    // ---- main loop: 64 chunks x 8 steps ----------------------------------
    for (int c = 0; c < NCHUNK; ++c) {
        const int pb = c & 1;                  // processing buffer
        const int nb = pb ^ 1;                 // next-chunk buffer

        // STS chunk c+1 (regs, LDG'd one chunk ago) -> buf nb
        {
            float4* dst = reinterpret_cast<float4*>(fbuf[nb][srow]);
#pragma unroll
            for (int k = 0; k < 4; ++k)
                dst[scol + 16 * k] = rv[k];
            mkbuf[nb][mt][mb] = rm;
        }
        __syncthreads();                       // chunk c+1 visible

        // LDG chunk c+2 -> regs (consumed one full chunk later)
        {
            const int t2 = ((c + 2) * CHUNK) & (SEQ - 1);
#pragma unroll
            for (int k = 0; k < 4; ++k)
                rv[k] = F4[(t2 + srow) * rs4 + cb4 + scol + 16 * k];
            rm = mask[(t2 + mt) * BATCH + bblk + mb];
        }

#pragma unroll
        for (int u = 0; u < CHUNK; ++u) {
            const u64 emc = em2, omc = om2;
            const float mcx = mxx, mcy = myy;

            // prep em/om for step u+1 (u==7 -> chunk c+1, slot 0)
            {
                const float* fsrc = (u + 1 < CHUNK) ? fbuf[pb][u + 1]
                                                    : fbuf[nb][0];
                const float* msrc = (u + 1 < CHUNK) ? mkbuf[pb][u + 1]
                                                    : mkbuf[nb][0];
                mxx = msrc[2 * w];
                myy = msrc[2 * w + 1];
                em2 = pack2(mxx * __expf(fsrc[2 * w * TAGS + j]),
                            myy * __expf(fsrc[(2 * w + 1) * TAGS + j]));
                om2 = pack2(1.0f - mxx, 1.0f - myy);
            }

            asm volatile("" ::: "memory");     // keep prior STS before LDS

            // q2[j] = sum_i e2[i]*P[i] : 16 broadcast LDS.128, 4 accums
            const ulonglong2* __restrict__ src =
                reinterpret_cast<const ulonglong2*>(sp[w]);
            u64 a0 = 0, a1 = 0, a2 = 0, a3 = 0;
#pragma unroll
            for (int h = 0; h < 4; ++h) {
                const ulonglong2 v0 = src[4 * h + 0];
                const ulonglong2 v1 = src[4 * h + 1];
                const ulonglong2 v2 = src[4 * h + 2];
                const ulonglong2 v3 = src[4 * h + 3];
                a0 = fma2(e2[8 * h + 0], v0.x, a0);
                a1 = fma2(e2[8 * h + 1], v0.y, a1);
                a2 = fma2(e2[8 * h + 2], v1.x, a2);
                a3 = fma2(e2[8 * h + 3], v1.y, a3);
                a0 = fma2(e2[8 * h + 4], v2.x, a0);
                a1 = fma2(e2[8 * h + 5], v2.y, a1);
                a2 = fma2(e2[8 * h + 6], v3.x, a2);
                a3 = fma2(e2[8 * h + 7], v3.y, a3);
            }
            const u64 q2 = add2(add2(a0, a1), add2(a2, a3));

            // packed tail: p' = q*em + p*om
            p2 = fma2(q2, emc, mul2(p2, omc));

            // applied-step counters (off-chain)
            cnt0 += mcx;
            cnt1 += mcy;

            // delayed renorm, period 16 (end of odd chunks)
            if ((c & 1) == 1 && u == CHUNK - 1) {
                p2 = mul2(p2, pinv2);          // apply PREVIOUS scale
                float sx, sy; unpack2(p2, sx, sy);
#pragma unroll
                for (int off = 16; off > 0; off >>= 1) {
                    const float tx = __shfl_xor_sync(0xffffffffu, sx, off);
                    const float ty = __shfl_xor_sync(0xffffffffu, sy, off);
                    sx = fmaxf(sx, tx);
                    sy = fmaxf(sy, ty);
                }
                M0 += __logf(sx);
                M1 += __logf(sy);
                pinv2 = pack2(__frcp_rn(sx), __frcp_rn(sy));
            }

            sp[w][j] = p2;                     // publish for next step
        }
        __syncthreads();                       // reads done before next STS
    }

    // ---- epilogue --------------------------------------------------------
    p2 = mul2(p2, pinv2);                      // final pending scale
    float px, py; unpack2(p2, px, py);
    float ax = px * eEnd;
    float ay = py * eEnd;
#pragma unroll
    for (int off = 16; off > 0; off >>= 1) {
        ax += __shfl_xor_sync(0xffffffffu, ax, off);
        ay += __shfl_xor_sync(0xffffffffu, ay, off);
    }
    if (j == 0) {
        out[b0]     = M0 + __logf(ax) + cnt0 * LOG_CPREINV;
        out[b0 + 1] = M1 + __logf(ay) + cnt1 * LOG_CPREINV;
    }
}

extern "C" void kernel_launch(void* const* d_in, const int* in_sizes, int n_in,
                              void* d_out, int out_size)
{
    const float* feats = (const float*)d_in[0];
    const float* msk   = (const float*)d_in[1];
    const float* trans = (const float*)d_in[2];
    float*       o     = (float*)d_out;

    crf_fwd_kernel<<<NBLOCKS, TPB>>>(feats, msk, trans, o);
}